// round 17
// baseline (speedup 1.0000x reference)
#include <cuda_runtime.h>
#include <math.h>

// Problem constants (fixed by reference)
#define B_   8
#define T_   4096
#define D_   64
#define R_   64
#define BT_  (B_ * T_)           // 32768 tokens
#define STRENGTH 0.1f
#define PHI_SCALE 0.17677669529663689f   // sqrt(2/64)
#define K1BLK 1024                // K1 blocks, 32 tokens each
#define WPAD 68                   // padded row stride (floats); 272B rows

// Scratch (static device globals — allocation-free)
__device__ float g_phi[BT_ * R_];          // 8 MB
__device__ float g_part[K1BLK * R_];       // per-block phi_sum partials
__device__ float g_phisum[B_ * R_];        // 2 KB

typedef unsigned long long u64;

__device__ __forceinline__ void unpack2(u64 v, float& lo, float& hi) {
    unsigned a, b;
    asm("mov.b64 {%0, %1}, %2;" : "=r"(a), "=r"(b) : "l"(v));
    lo = __uint_as_float(a); hi = __uint_as_float(b);
}
__device__ __forceinline__ u64 ffma2(u64 a, u64 b, u64 c) {
    u64 d;
    asm("fma.rn.f32x2 %0, %1, %2, %3;" : "=l"(d) : "l"(a), "l"(b), "l"(c));
    return d;
}

// ---------------------------------------------------------------------------
// K1: thread = (token, octet). 1024 blocks x 256 threads; block = 32 tokens.
// lane = (tok4 << 3) | p : 4 tokens/warp, 8 output-octets each.
// Weights stored ROW-PERMUTED (slot = (r&7)*8 + (r>>3)) so the 8 per-lane
// addresses of every weight LDS.128 land on 8 distinct 16B crossbar segments
// (272B spacing -> bank offsets 0,16,...,112) = ONE phase, no conflicts.
// Coords in registers as natural (c_d, c_{d+1}) u64 pairs from LDG.128.
// ---------------------------------------------------------------------------
__global__ __launch_bounds__(256)
void k1_phi_mass(const float* __restrict__ coords,
                 const float* __restrict__ w1, const float* __restrict__ b1,
                 const float* __restrict__ w2, const float* __restrict__ b2,
                 const float* __restrict__ W,  const float* __restrict__ b)
{
    __shared__ __align__(16) float Wt[R_ * WPAD];   // permuted rows of W^T (17.4KB)
    __shared__ __align__(16) float Ht[D_ * WPAD];   // permuted rows of w1   (17.4KB)
    __shared__ float bsh[R_], b1sh[D_], w2sh[D_];
    __shared__ float psh[8][R_];

    const int tid  = threadIdx.x;
    const int wid  = tid >> 5;          // 0..7
    const int lane = tid & 31;
    const int p    = lane & 7;          // output octet 0..7
    const int tok  = blockIdx.x * 32 + (tid >> 3);   // 32 tokens per block

    // ---- stage weights, row-permuted ----
    for (int i = tid; i < D_ * R_; i += 256) {
        const int d = i >> 6, r = i & 63;
        Wt[(((r & 7) << 3) | (r >> 3)) * WPAD + d] = W[i];       // W[d][r] -> row r
    }
    for (int i = tid; i < D_ * D_; i += 256) {
        const int j = i >> 6, d = i & 63;
        Ht[(((j & 7) << 3) | (j >> 3)) * WPAD + d] = w1[i];      // w1[j][d] -> row j
    }
    if (tid < 64) { bsh[tid] = b[tid]; b1sh[tid] = b1[tid]; w2sh[tid] = w2[tid]; }
    const float b2v = b2[0];

    // ---- coords for this thread's token (8 lanes share -> L1 broadcast) ----
    ulonglong2 cc[16];
    {
        const ulonglong2* csrc = (const ulonglong2*)(coords + (size_t)tok * D_);
        #pragma unroll
        for (int i = 0; i < 16; ++i) cc[i] = __ldg(&csrc[i]);
    }
    __syncthreads();

    // ============ mass-net: this thread's 8 j's = p*8 .. p*8+7 =============
    float macc = 0.0f;
    #pragma unroll
    for (int jg = 0; jg < 2; ++jg) {
        u64 a0 = 0, a1 = 0, a2 = 0, a3 = 0;
        // row slots: (jg*4+row4)*8 + p  -> consecutive-slot spread, 1 phase
        const float* h0 = &Ht[((jg * 4 + 0) * 8 + p) * WPAD];
        const float* h1 = &Ht[((jg * 4 + 1) * 8 + p) * WPAD];
        const float* h2 = &Ht[((jg * 4 + 2) * 8 + p) * WPAD];
        const float* h3 = &Ht[((jg * 4 + 3) * 8 + p) * WPAD];
        #pragma unroll
        for (int d4 = 0; d4 < 16; ++d4) {
            const ulonglong2 w0 = *(const ulonglong2*)&h0[d4 * 4];
            const ulonglong2 w1r = *(const ulonglong2*)&h1[d4 * 4];
            const ulonglong2 w2r = *(const ulonglong2*)&h2[d4 * 4];
            const ulonglong2 w3r = *(const ulonglong2*)&h3[d4 * 4];
            const u64 ca = cc[d4].x, cb = cc[d4].y;
            a0 = ffma2(ca, w0.x,  a0); a0 = ffma2(cb, w0.y,  a0);
            a1 = ffma2(ca, w1r.x, a1); a1 = ffma2(cb, w1r.y, a1);
            a2 = ffma2(ca, w2r.x, a2); a2 = ffma2(cb, w2r.y, a2);
            a3 = ffma2(ca, w3r.x, a3); a3 = ffma2(cb, w3r.y, a3);
        }
        const int j0 = p * 8 + jg * 4;
        const float4 b1v = *(const float4*)&b1sh[j0];
        const float4 w2v = *(const float4*)&w2sh[j0];
        float lo, hi;
        unpack2(a0, lo, hi); macc = fmaf(fmaxf(lo + hi + b1v.x, 0.0f), w2v.x, macc);
        unpack2(a1, lo, hi); macc = fmaf(fmaxf(lo + hi + b1v.y, 0.0f), w2v.y, macc);
        unpack2(a2, lo, hi); macc = fmaf(fmaxf(lo + hi + b1v.z, 0.0f), w2v.z, macc);
        unpack2(a3, lo, hi); macc = fmaf(fmaxf(lo + hi + b1v.w, 0.0f), w2v.w, macc);
    }
    // combine the 8 octets of this token (lanes differ in bits 0..2)
    macc += __shfl_xor_sync(0xffffffffu, macc, 1);
    macc += __shfl_xor_sync(0xffffffffu, macc, 2);
    macc += __shfl_xor_sync(0xffffffffu, macc, 4);
    const float x = macc + b2v;
    const float mass = fmaxf(x, 0.0f) + log1pf(expf(-fabsf(x)));  // stable softplus

    // ============ RFF: this thread's 8 r's = p*8 .. p*8+7 ===================
    #pragma unroll
    for (int g = 0; g < 2; ++g) {
        u64 a0 = 0, a1 = 0, a2 = 0, a3 = 0;
        const float* q0 = &Wt[((g * 4 + 0) * 8 + p) * WPAD];
        const float* q1 = &Wt[((g * 4 + 1) * 8 + p) * WPAD];
        const float* q2 = &Wt[((g * 4 + 2) * 8 + p) * WPAD];
        const float* q3 = &Wt[((g * 4 + 3) * 8 + p) * WPAD];
        #pragma unroll
        for (int d4 = 0; d4 < 16; ++d4) {
            const ulonglong2 w0 = *(const ulonglong2*)&q0[d4 * 4];
            const ulonglong2 w1r = *(const ulonglong2*)&q1[d4 * 4];
            const ulonglong2 w2r = *(const ulonglong2*)&q2[d4 * 4];
            const ulonglong2 w3r = *(const ulonglong2*)&q3[d4 * 4];
            const u64 ca = cc[d4].x, cb = cc[d4].y;
            a0 = ffma2(ca, w0.x,  a0); a0 = ffma2(cb, w0.y,  a0);
            a1 = ffma2(ca, w1r.x, a1); a1 = ffma2(cb, w1r.y, a1);
            a2 = ffma2(ca, w2r.x, a2); a2 = ffma2(cb, w2r.y, a2);
            a3 = ffma2(ca, w3r.x, a3); a3 = ffma2(cb, w3r.y, a3);
        }
        const int r0 = p * 8 + g * 4;
        const float4 bv = *(const float4*)&bsh[r0];
        float lo, hi;
        float4 ph;
        unpack2(a0, lo, hi); ph.x = PHI_SCALE * __cosf(lo + hi + bv.x);
        unpack2(a1, lo, hi); ph.y = PHI_SCALE * __cosf(lo + hi + bv.y);
        unpack2(a2, lo, hi); ph.z = PHI_SCALE * __cosf(lo + hi + bv.z);
        unpack2(a3, lo, hi); ph.w = PHI_SCALE * __cosf(lo + hi + bv.w);
        *(float4*)&g_phi[(size_t)tok * R_ + r0] = ph;

        // phi*mass summed over the 4 tokens of this warp (lanes: bits 3,4)
        float p0 = ph.x * mass, p1 = ph.y * mass, p2 = ph.z * mass, p3 = ph.w * mass;
        #pragma unroll
        for (int off = 8; off <= 16; off <<= 1) {
            p0 += __shfl_xor_sync(0xffffffffu, p0, off);
            p1 += __shfl_xor_sync(0xffffffffu, p1, off);
            p2 += __shfl_xor_sync(0xffffffffu, p2, off);
            p3 += __shfl_xor_sync(0xffffffffu, p3, off);
        }
        if (lane < 8)                            // lane == p for token-slot 0
            *(float4*)&psh[wid][r0] = make_float4(p0, p1, p2, p3);
    }
    __syncthreads();
    if (tid < 64) {
        float s = 0.0f;
        #pragma unroll
        for (int w = 0; w < 8; ++w) s += psh[w][tid];
        g_part[blockIdx.x * R_ + tid] = s;
    }
}

// ---------------------------------------------------------------------------
// K2: reduce 128 block-partials per (batch, r) in fixed order. <<<8, 64>>>
// (blocks per batch = 4096 tokens / 32 tokens-per-block = 128)
// ---------------------------------------------------------------------------
__global__ void k2_reduce_phisum()
{
    const int batch = blockIdx.x;
    const int r = threadIdx.x;
    float s = 0.0f;
    #pragma unroll 8
    for (int c = 0; c < 128; ++c)
        s += g_part[(batch * 128 + c) * R_ + r];
    g_phisum[batch * R_ + r] = s;
}

// ---------------------------------------------------------------------------
// K4: grav (warp 0) + streaming copy of G with diagonal add.
// Block per token (32768 blocks), 256 threads — unchanged (86% DRAM, proven).
// ---------------------------------------------------------------------------
__global__ __launch_bounds__(256)
void k4_copy(const float4* __restrict__ G4, float4* __restrict__ out4)
{
    const int tok = blockIdx.x;
    __shared__ float gsh;

    if (threadIdx.x < 32) {
        const int lane = threadIdx.x;
        const int batch = tok >> 12;                 // T = 4096
        const float* ph = g_phi    + (size_t)tok * R_;
        const float* ps = g_phisum + batch * R_;
        float s = ph[lane] * ps[lane] + ph[lane + 32] * ps[lane + 32];
        #pragma unroll
        for (int off = 16; off > 0; off >>= 1)
            s += __shfl_down_sync(0xffffffffu, s, off);
        if (lane == 0) gsh = STRENGTH * s;
    }
    __syncthreads();
    const float g = gsh;

    const float4* src = G4   + (size_t)tok * 1024;   // 4096 floats
    float4*       dst = out4 + (size_t)tok * 1024;

    float4 v[4];
    #pragma unroll
    for (int i = 0; i < 4; ++i)
        v[i] = __ldcs(&src[threadIdx.x + i * 256]);  // batched streaming loads

    #pragma unroll
    for (int i = 0; i < 4; ++i) {
        const int idx = threadIdx.x + i * 256;
        const int lin = idx << 2;
        float4 x = v[i];
        if (((lin    ) >> 6) == ((lin    ) & 63)) x.x += g;
        if (((lin + 1) >> 6) == ((lin + 1) & 63)) x.y += g;
        if (((lin + 2) >> 6) == ((lin + 2) & 63)) x.z += g;
        if (((lin + 3) >> 6) == ((lin + 3) & 63)) x.w += g;
        __stcs(&dst[idx], x);                        // streaming stores
    }
}

// ---------------------------------------------------------------------------
extern "C" void kernel_launch(void* const* d_in, const int* in_sizes, int n_in,
                              void* d_out, int out_size)
{
    const float* G      = (const float*)d_in[0];
    const float* coords = (const float*)d_in[1];
    const float* w1     = (const float*)d_in[2];
    const float* b1     = (const float*)d_in[3];
    const float* w2     = (const float*)d_in[4];
    const float* b2     = (const float*)d_in[5];
    const float* W      = (const float*)d_in[6];
    const float* b      = (const float*)d_in[7];
    float* out = (float*)d_out;

    k1_phi_mass<<<K1BLK, 256>>>(coords, w1, b1, w2, b2, W, b);
    k2_reduce_phisum<<<8, 64>>>();
    k4_copy<<<BT_, 256>>>((const float4*)G, (float4*)out);
}